// round 17
// baseline (speedup 1.0000x reference)
#include <cuda_runtime.h>
#include <math.h>

#define N_NODES  100000
#define N_EDGES  1600000
#define NG       64
#define F0       32
#define F1       16
#define F2       8
#define NC       6
#define CAP      64           // ELL capacity; P(Poisson(16)>64) ~ 1e-20
#define GRID_P   1184         // persistent grid = exactly 8 blocks/SM * 148 SMs
#define NWARPS   (GRID_P * 8)
#define CHUNK    ((N_NODES + NWARPS - 1) / NWARPS)   // 11 contiguous nodes/warp
#define NPAIR    ((CHUNK + 1) / 2)

// ---------------- scratch (device globals) ----------------------------------
__device__ int   g_deg[N_NODES];
__device__ int   g_ell[(size_t)N_NODES * CAP];   // ELL src lists
__device__ float g_y [N_NODES * F1];             // x @ W1a   (pre-agg transform)
__device__ float g_z [N_NODES * F2];             // h1 @ W2a  (pre-agg transform)
__device__ float g_pool[NG * F2];
__device__ float g_cnt[NG];
__device__ int   g_done;

// ---------------- kernels ---------------------------------------------------

// merged: zero scratch + dense y = x @ W1a (no bias; added post-agg)
__global__ void __launch_bounds__(256)
k_zx(const float* __restrict__ x, const float* __restrict__ W1a) {
    __shared__ float sW[F0 * F1];
    int tid = threadIdx.x;
    for (int i = tid; i < F0 * F1; i += 256) sW[i] = W1a[i];
    __syncthreads();

    int idx = blockIdx.x * 256 + tid;
    if (idx < N_NODES) g_deg[idx] = 0;
    if (idx < NG * F2) g_pool[idx] = 0.f;
    if (idx < NG)      g_cnt[idx]  = 0.f;
    if (idx == 0)      g_done = 0;

    if (idx >= N_NODES * F1) return;
    int n = idx >> 4;
    int j = idx & 15;
    const float4* xr = (const float4*)(x + n * F0);
    float acc = 0.f;
#pragma unroll
    for (int f4 = 0; f4 < 8; ++f4) {
        float4 v = __ldg(xr + f4);
        acc += v.x * sW[(f4 * 4 + 0) * F1 + j];
        acc += v.y * sW[(f4 * 4 + 1) * F1 + j];
        acc += v.z * sW[(f4 * 4 + 2) * F1 + j];
        acc += v.w * sW[(f4 * 4 + 3) * F1 + j];
    }
    g_y[idx] = acc;
}

// vectorized ELL fill: 4 edges per thread via int4
__global__ void __launch_bounds__(256)
k_fill(const int* __restrict__ src, const int* __restrict__ dst) {
    int t = blockIdx.x * blockDim.x + threadIdx.x;
    int e4 = t * 4;
    if (e4 >= N_EDGES) return;
    int4 s4 = *(const int4*)(src + e4);
    int4 d4 = *(const int4*)(dst + e4);
#pragma unroll
    for (int i = 0; i < 4; ++i) {
        int d = (i == 0) ? d4.x : (i == 1) ? d4.y : (i == 2) ? d4.z : d4.w;
        int s = (i == 0) ? s4.x : (i == 1) ? s4.y : (i == 2) ? s4.z : s4.w;
        int p = atomicAdd(&g_deg[d], 1);
        if (p < CAP) g_ell[(size_t)d * CAP + p] = s;
    }
}

// ===== fused gather(y)+mlp1+emit z — TWO nodes per warp =====================
__global__ void __launch_bounds__(256, 8)
k_g1m1(const float* __restrict__ b1a,
       const float* __restrict__ W1b, const float* __restrict__ b1b,
       const float* __restrict__ W2a) {
    __shared__ float sWb[F1 * 17];       // [k][j] stride 17
    __shared__ float sWz[F1 * 9];        // [k][j8] stride 9
    __shared__ float sba[F1], sbb[F1];
    __shared__ float sh[8][2][F1];       // pre-activation per (warp, half)
    __shared__ float st[8][2][F1];       // relu(layer1)
    __shared__ float su[8][2][F1];       // h1

    int tid  = threadIdx.x;
    int wid  = tid >> 5;
    int lane = tid & 31;
    int nh   = lane >> 4;                // node half
    int r    = lane & 15;
    int slot = r >> 2;                   // 0..3 edge slot
    int q    = r & 3;                    // row quarter (float4)
    int j8   = r & 7;
    int kh   = r >> 3;

    for (int i = tid; i < F1 * F1; i += 256) sWb[(i >> 4) * 17 + (i & 15)] = W1b[i];
    for (int i = tid; i < F1 * F2; i += 256) sWz[(i >> 3) * 9  + (i & 7)]  = W2a[i];
    if (tid < F1) { sba[tid] = b1a[tid]; sbb[tid] = b1b[tid]; }
    __syncthreads();

    int wg = blockIdx.x * 8 + wid;
    int w0 = wg * CHUNK;
    int w1 = w0 + CHUNK; if (w1 > N_NODES) w1 = N_NODES;
    const float4* yr = (const float4*)g_y;

    for (int p = 0; p < NPAIR; ++p) {
        int w = w0 + 2 * p + nh;
        bool valid = (w < w1);
        int deg = valid ? g_deg[w] : 0;
        if (deg > CAP) deg = CAP;
        const int* el = g_ell + (size_t)w * CAP;

        float4 a4 = make_float4(0.f, 0.f, 0.f, 0.f);
        int e = 0;
#pragma unroll 2
        for (; e + 4 <= deg; e += 4) {
            int s = __ldg(&el[e + slot]);
            float4 v = __ldg(yr + s * 4 + q);
            a4.x += v.x; a4.y += v.y; a4.z += v.z; a4.w += v.w;
        }
        if (slot < deg - e) {
            int s = __ldg(&el[e + slot]);
            float4 v = __ldg(yr + s * 4 + q);
            a4.x += v.x; a4.y += v.y; a4.z += v.z; a4.w += v.w;
        }
#pragma unroll
        for (int off = 8; off >= 4; off >>= 1) {
            a4.x += __shfl_down_sync(0xffffffffu, a4.x, off);
            a4.y += __shfl_down_sync(0xffffffffu, a4.y, off);
            a4.z += __shfl_down_sync(0xffffffffu, a4.z, off);
            a4.w += __shfl_down_sync(0xffffffffu, a4.w, off);
        }
        if (r < 4 && valid) {
            float4 ys = __ldg(yr + w * 4 + r);
            a4.x += ys.x; a4.y += ys.y; a4.z += ys.z; a4.w += ys.w;
            ((float4*)sh[wid][nh])[r] = a4;
        }
        __syncwarp();

        // layer-1 activation (matmul folded into y)
        st[wid][nh][r] = fmaxf(sh[wid][nh][r] + sba[r], 0.f);
        __syncwarp();

        // layer 2: 16->16 full-sum per lane; outer relu fused -> h1
        float part = sbb[r];
#pragma unroll
        for (int k = 0; k < 16; ++k)
            part += st[wid][nh][k] * sWb[k * 17 + r];
        su[wid][nh][r] = fmaxf(part, 0.f);
        __syncwarp();

        // z = h1 @ W2a : 16->8 per half, k split across kh
        float pz = 0.f;
#pragma unroll
        for (int k = 0; k < 8; ++k)
            pz += su[wid][nh][kh * 8 + k] * sWz[(kh * 8 + k) * 9 + j8];
        pz += __shfl_down_sync(0xffffffffu, pz, 8);
        if (r < 8 && valid) g_z[w * F2 + j8] = pz;
        __syncwarp();
    }
}

// ===== fused gather(z)+mlp2+pool+HEAD — TWO nodes per warp ==================
__global__ void __launch_bounds__(256, 8)
k_g2m2p(const float* __restrict__ b2a,
        const float* __restrict__ W2b, const float* __restrict__ b2b,
        const int* __restrict__ batch,
        const float* __restrict__ Wfc, const float* __restrict__ bfc,
        float* __restrict__ out) {
    __shared__ float sWb[F2 * 9];        // [k][j8] stride 9
    __shared__ float sba[F2], sbb[F2];
    __shared__ float sh[8][2][F2];
    __shared__ float st[8][2][F2];
    __shared__ float sp[NG * F2];
    __shared__ float sc[NG];
    __shared__ int   s_last;

    int tid  = threadIdx.x;
    int wid  = tid >> 5;
    int lane = tid & 31;
    int nh   = lane >> 4;
    int r    = lane & 15;
    int slot = r >> 1;                   // 0..7 edge slot
    int q    = r & 1;                    // row half (float4)
    int j8   = r & 7;

    for (int i = tid; i < F2 * F2; i += 256) sWb[(i >> 3) * 9 + (i & 7)] = W2b[i];
    if (tid < F2) { sba[tid] = b2a[tid]; sbb[tid] = b2b[tid]; }
    for (int i = tid; i < NG * F2; i += 256) sp[i] = 0.f;
    for (int i = tid; i < NG;      i += 256) sc[i] = 0.f;
    __syncthreads();

    int wg = blockIdx.x * 8 + wid;
    int w0 = wg * CHUNK;
    int w1 = w0 + CHUNK; if (w1 > N_NODES) w1 = N_NODES;
    const float4* zr = (const float4*)g_z;

    float pacc = 0.f, prun = 0.f;
    int   cur_b = ((w0 + nh) < w1) ? __ldg(&batch[w0 + nh]) : 0;

    for (int p = 0; p < NPAIR; ++p) {
        int w = w0 + 2 * p + nh;
        bool valid = (w < w1);
        int deg = valid ? g_deg[w] : 0;
        if (deg > CAP) deg = CAP;
        const int* el = g_ell + (size_t)w * CAP;

        float4 a4 = make_float4(0.f, 0.f, 0.f, 0.f);
        int e = 0;
        for (; e + 8 <= deg; e += 8) {
            int s = __ldg(&el[e + slot]);
            float4 v = __ldg(zr + s * 2 + q);
            a4.x += v.x; a4.y += v.y; a4.z += v.z; a4.w += v.w;
        }
        if (slot < deg - e) {
            int s = __ldg(&el[e + slot]);
            float4 v = __ldg(zr + s * 2 + q);
            a4.x += v.x; a4.y += v.y; a4.z += v.z; a4.w += v.w;
        }
#pragma unroll
        for (int off = 8; off >= 2; off >>= 1) {
            a4.x += __shfl_down_sync(0xffffffffu, a4.x, off);
            a4.y += __shfl_down_sync(0xffffffffu, a4.y, off);
            a4.z += __shfl_down_sync(0xffffffffu, a4.z, off);
            a4.w += __shfl_down_sync(0xffffffffu, a4.w, off);
        }
        if (r < 2 && valid) {
            float4 zs = __ldg(zr + w * 2 + r);
            a4.x += zs.x; a4.y += zs.y; a4.z += zs.z; a4.w += zs.w;
            ((float4*)sh[wid][nh])[r] = a4;
        }
        __syncwarp();

        if (r < F2) st[wid][nh][j8] = fmaxf(sh[wid][nh][j8] + sba[j8], 0.f);
        __syncwarp();

        int b = valid ? __ldg(&batch[w]) : cur_b;
        if (b != cur_b) {
            if (r < F2 && prun > 0.f) {
                atomicAdd(&sp[cur_b * F2 + j8], pacc);
                if (r == 0) atomicAdd(&sc[cur_b], prun);
            }
            pacc = 0.f; prun = 0.f; cur_b = b;
        }
        if (r < F2) {
            float o = sbb[j8];
#pragma unroll
            for (int k = 0; k < 8; ++k)
                o += st[wid][nh][k] * sWb[k * 9 + j8];
            if (valid) pacc += fmaxf(o, 0.f);
        }
        if (valid) prun += 1.f;
        __syncwarp();
    }
    if (r < F2 && prun > 0.f) {
        atomicAdd(&sp[cur_b * F2 + j8], pacc);
        if (r == 0) atomicAdd(&sc[cur_b], prun);
    }

    __syncthreads();
    for (int i = tid; i < NG * F2; i += 256)
        if (sp[i] != 0.f) atomicAdd(&g_pool[i], sp[i]);
    for (int i = tid; i < NG; i += 256)
        if (sc[i] != 0.f) atomicAdd(&g_cnt[i], sc[i]);

    // ---- last-block head: log_softmax(pooled @ Wfc + bfc) ----
    __threadfence();
    if (tid == 0) {
        int t = atomicAdd(&g_done, 1);
        s_last = (t == GRID_P - 1) ? 1 : 0;
    }
    __syncthreads();
    if (s_last && tid < NG) {
        int g = tid;
        float c = g_cnt[g];
        c = (c < 1.f) ? 1.f : c;
        float pm[F2];
#pragma unroll
        for (int j = 0; j < F2; ++j) pm[j] = g_pool[g * F2 + j] / c;
        float l[NC];
#pragma unroll
        for (int j = 0; j < NC; ++j) {
            float a = __ldg(&bfc[j]);
#pragma unroll
            for (int f = 0; f < F2; ++f) a += pm[f] * __ldg(&Wfc[f * NC + j]);
            l[j] = a;
        }
        float m = l[0];
#pragma unroll
        for (int j = 1; j < NC; ++j) m = fmaxf(m, l[j]);
        float s = 0.f;
#pragma unroll
        for (int j = 0; j < NC; ++j) s += expf(l[j] - m);
        float ls = logf(s);
#pragma unroll
        for (int j = 0; j < NC; ++j) out[g * NC + j] = l[j] - m - ls;
    }
}

// ---------------- launch ----------------------------------------------------

extern "C" void kernel_launch(void* const* d_in, const int* in_sizes, int n_in,
                              void* d_out, int out_size) {
    const float* x   = (const float*)d_in[0];
    const int*   ei  = (const int*)d_in[1];     // [2, E] int32
    const int*   bat = (const int*)d_in[2];     // int32
    const float* W1a = (const float*)d_in[3];
    const float* b1a = (const float*)d_in[4];
    const float* W1b = (const float*)d_in[5];
    const float* b1b = (const float*)d_in[6];
    const float* W2a = (const float*)d_in[7];
    const float* b2a = (const float*)d_in[8];
    const float* W2b = (const float*)d_in[9];
    const float* b2b = (const float*)d_in[10];
    const float* Wfc = (const float*)d_in[11];
    const float* bfc = (const float*)d_in[12];
    float* out = (float*)d_out;

    const int* src = ei;
    const int* dst = ei + N_EDGES;

    const int BS = 256;
    int gb_zx   = (N_NODES * F1 + BS - 1) / BS;
    int gb_fill = (N_EDGES / 4 + BS - 1) / BS;

    k_zx    <<<gb_zx, BS>>>(x, W1a);
    k_fill  <<<gb_fill, BS>>>(src, dst);
    k_g1m1  <<<GRID_P, BS>>>(b1a, W1b, b1b, W2a);
    k_g2m2p <<<GRID_P, BS>>>(b2a, W2b, b2b, bat, Wfc, bfc, out);
}